// round 2
// baseline (speedup 1.0000x reference)
#include <cuda_runtime.h>
#include <cstddef>
#include <cstdint>
#include <math.h>

#define BATCH 128

// ---------------------------------------------------------------------------
// Scratch: one big __device__ array (no allocations allowed).
// ---------------------------------------------------------------------------
constexpr size_t N_BUF1 = (size_t)BATCH * 96 * 32 * 32;   // conv1 out
constexpr size_t N_BUF2 = (size_t)BATCH * 96 * 16 * 16;   // pool1
constexpr size_t N_BUF3 = (size_t)BATCH * 256 * 16 * 16;  // conv2 out
constexpr size_t N_BUF4 = (size_t)BATCH * 256 * 8 * 8;    // pool2
constexpr size_t N_BUF5 = (size_t)BATCH * 384 * 8 * 8;    // conv3 out
constexpr size_t N_BUF6 = (size_t)BATCH * 256 * 6 * 6;    // pcaps out
constexpr size_t N_U    = (size_t)BATCH * 1152 * 8;       // squashed caps
constexpr size_t N_XHAT = (size_t)BATCH * 100 * 1152 * 16;
constexpr size_t N_BLOG = (size_t)BATCH * 100 * 1152;
constexpr size_t N_C    = (size_t)BATCH * 100 * 1152;
constexpr size_t N_V    = (size_t)BATCH * 100 * 16;
constexpr size_t N_F1   = (size_t)BATCH * 4096;
constexpr size_t N_F2   = (size_t)BATCH * 4096;

constexpr size_t O_BUF1 = 0;
constexpr size_t O_BUF2 = O_BUF1 + N_BUF1;
constexpr size_t O_BUF3 = O_BUF2 + N_BUF2;
constexpr size_t O_BUF4 = O_BUF3 + N_BUF3;
constexpr size_t O_BUF5 = O_BUF4 + N_BUF4;
constexpr size_t O_BUF6 = O_BUF5 + N_BUF5;
constexpr size_t O_U    = O_BUF6 + N_BUF6;
constexpr size_t O_XHAT = O_U + N_U;
constexpr size_t O_BLOG = O_XHAT + N_XHAT;
constexpr size_t O_C    = O_BLOG + N_BLOG;
constexpr size_t O_V    = O_C + N_C;
constexpr size_t O_F1   = O_V + N_V;
constexpr size_t O_F2   = O_F1 + N_F1;
constexpr size_t N_TOTAL = O_F2 + N_F2;

__device__ __align__(16) float g_scratch[N_TOTAL];

// ---------------------------------------------------------------------------
// Generic direct 3x3 conv (stride 1). Register-blocked: each thread computes
// PPT consecutive pixels in a row x 8 output channels.
//   threads = (HOUT*WOUT/PPT) * NOCSUB ; block covers NOCSUB*8 out channels.
// ---------------------------------------------------------------------------
template<int CIN, int HIN, int WIN, int COUT, int HOUT, int WOUT, int PAD,
         int ICC, int PPT, int NOCSUB, bool RELU>
__global__ void conv3x3_kernel(const float* __restrict__ in,
                               const float* __restrict__ wt,
                               const float* __restrict__ bias,
                               float* __restrict__ out)
{
    constexpr int NPG = (HOUT * WOUT) / PPT;
    constexpr int NT  = NPG * NOCSUB;
    constexpr int OCB = NOCSUB * 8;
    constexpr int HT  = HIN + 2 * PAD;
    constexpr int WT  = WIN + 2 * PAD;
    constexpr int WTP = WT + 1;

    __shared__ __align__(16) float in_s[ICC * HT * WTP];
    __shared__ __align__(16) float w_s[ICC * 9 * OCB];

    const int tid   = threadIdx.x;
    const int ocblk = blockIdx.x;
    const int b     = blockIdx.y;

    const int pg   = tid % NPG;
    const int ocs  = tid / NPG;
    const int row  = pg / (WOUT / PPT);
    const int col0 = (pg % (WOUT / PPT)) * PPT;
    const int oc0  = ocblk * OCB + ocs * 8;

    float acc[PPT][8];
    #pragma unroll
    for (int j = 0; j < 8; j++) {
        float bj = bias[oc0 + j];
        #pragma unroll
        for (int p = 0; p < PPT; p++) acc[p][j] = bj;
    }

    for (int ic0 = 0; ic0 < CIN; ic0 += ICC) {
        __syncthreads();
        // input tile (with zero padding)
        for (int idx = tid; idx < ICC * HT * WT; idx += NT) {
            int x  = idx % WT;
            int y  = (idx / WT) % HT;
            int ic = idx / (WT * HT);
            int gy = y - PAD, gx = x - PAD;
            float v = 0.f;
            if (gy >= 0 && gy < HIN && gx >= 0 && gx < WIN)
                v = in[((size_t)(b * CIN + ic0 + ic) * HIN + gy) * WIN + gx];
            in_s[(ic * HT + y) * WTP + x] = v;
        }
        // weights: global layout [oc][ic][3][3] -> smem [ic][tap][oc]
        for (int idx = tid; idx < ICC * 9 * OCB; idx += NT) {
            int oc_l = idx % OCB;
            int tap  = (idx / OCB) % 9;
            int ic   = idx / (OCB * 9);
            w_s[(ic * 9 + tap) * OCB + oc_l] =
                wt[((size_t)(ocblk * OCB + oc_l) * CIN + ic0 + ic) * 9 + tap];
        }
        __syncthreads();

        #pragma unroll
        for (int ic = 0; ic < ICC; ic++) {
            #pragma unroll
            for (int ky = 0; ky < 3; ky++) {
                #pragma unroll
                for (int kx = 0; kx < 3; kx++) {
                    const float4* wp = reinterpret_cast<const float4*>(
                        &w_s[(ic * 9 + ky * 3 + kx) * OCB + ocs * 8]);
                    float4 wA = wp[0];
                    float4 wB = wp[1];
                    #pragma unroll
                    for (int p = 0; p < PPT; p++) {
                        float xv = in_s[(ic * HT + row + ky) * WTP + col0 + p + kx];
                        acc[p][0] = fmaf(xv, wA.x, acc[p][0]);
                        acc[p][1] = fmaf(xv, wA.y, acc[p][1]);
                        acc[p][2] = fmaf(xv, wA.z, acc[p][2]);
                        acc[p][3] = fmaf(xv, wA.w, acc[p][3]);
                        acc[p][4] = fmaf(xv, wB.x, acc[p][4]);
                        acc[p][5] = fmaf(xv, wB.y, acc[p][5]);
                        acc[p][6] = fmaf(xv, wB.z, acc[p][6]);
                        acc[p][7] = fmaf(xv, wB.w, acc[p][7]);
                    }
                }
            }
        }
    }

    #pragma unroll
    for (int j = 0; j < 8; j++) {
        #pragma unroll
        for (int p = 0; p < PPT; p++) {
            float v = acc[p][j];
            if (RELU) v = fmaxf(v, 0.f);
            out[((size_t)(b * COUT + oc0 + j) * HOUT + row) * WOUT + col0 + p] = v;
        }
    }
}

// ---------------------------------------------------------------------------
// MaxPool 3x3 stride 2 pad 1 (torch semantics)
// ---------------------------------------------------------------------------
template<int C, int HIN>
__global__ void maxpool_kernel(const float* __restrict__ in, float* __restrict__ out)
{
    constexpr int HO = HIN / 2;
    int idx = blockIdx.x * blockDim.x + threadIdx.x;
    if (idx >= BATCH * C * HO * HO) return;
    int ox = idx % HO;
    int oy = (idx / HO) % HO;
    int c  = (idx / (HO * HO)) % C;
    int b  = idx / (HO * HO * C);
    const float* p = in + ((size_t)(b * C + c)) * HIN * HIN;
    float m = -1e30f;
    #pragma unroll
    for (int dy = 0; dy < 3; dy++) {
        int y = 2 * oy - 1 + dy;
        if (y < 0 || y >= HIN) continue;
        #pragma unroll
        for (int dx = 0; dx < 3; dx++) {
            int x = 2 * ox - 1 + dx;
            if (x < 0 || x >= HIN) continue;
            m = fmaxf(m, p[y * HIN + x]);
        }
    }
    out[idx] = m;
}

// ---------------------------------------------------------------------------
// Squash primarycaps: p flat [B,9216] -> u [B,1152,8]
// ---------------------------------------------------------------------------
__global__ void squash_u_kernel(const float* __restrict__ p, float* __restrict__ u)
{
    int cap = blockIdx.x * blockDim.x + threadIdx.x;
    if (cap >= BATCH * 1152) return;
    const float4* s = reinterpret_cast<const float4*>(p + (size_t)cap * 8);
    float4 a = s[0], b4 = s[1];
    float n2 = a.x * a.x + a.y * a.y + a.z * a.z + a.w * a.w +
               b4.x * b4.x + b4.y * b4.y + b4.z * b4.z + b4.w * b4.w;
    float sc = (n2 / (1.f + n2)) * rsqrtf(n2 + 1e-8f);
    float4* o = reinterpret_cast<float4*>(u + (size_t)cap * 8);
    o[0] = make_float4(a.x * sc, a.y * sc, a.z * sc, a.w * sc);
    o[1] = make_float4(b4.x * sc, b4.y * sc, b4.z * sc, b4.w * sc);
}

// ---------------------------------------------------------------------------
// x_hat[b,o,i,d] = sum_e W[o,i,d,e] * u[b,i,e]
// grid (36 i-chunks, 100 o); block 256. W chunk in smem, loop over batch.
// ---------------------------------------------------------------------------
__global__ void xhat_kernel(const float* __restrict__ Wc,
                            const float* __restrict__ u,
                            float* __restrict__ xhat)
{
    __shared__ float W_s[32 * 16 * 8];
    __shared__ float u_s[32 * 8];
    int o  = blockIdx.y;
    int i0 = blockIdx.x * 32;
    int tid = threadIdx.x;

    const float* wg = Wc + ((size_t)o * 1152 + i0) * 16 * 8;
    for (int idx = tid; idx < 32 * 16 * 8; idx += 256) W_s[idx] = wg[idx];
    __syncthreads();

    for (int b = 0; b < BATCH; b++) {
        u_s[tid] = u[((size_t)b * 1152 + i0) * 8 + tid];
        __syncthreads();
        #pragma unroll
        for (int rep = 0; rep < 2; rep++) {
            int t  = tid + rep * 256;
            int il = t >> 4;
            int d  = t & 15;
            const float* wrow = &W_s[(il * 16 + d) * 8];
            const float* urow = &u_s[il * 8];
            float acc = 0.f;
            #pragma unroll
            for (int e = 0; e < 8; e++) acc = fmaf(wrow[e], urow[e], acc);
            xhat[(((size_t)b * 100 + o) * 1152 + i0 + il) * 16 + d] = acc;
        }
        __syncthreads();
    }
}

// ---------------------------------------------------------------------------
// Routing: s[b,o,:] = sum_i c[b,o,i] * xhat[b,o,i,:]; v = squash(s)
// grid (100, B); block 256. use_c=0 means uniform coupling 1/100.
// ---------------------------------------------------------------------------
__global__ void route_s_kernel(const float* __restrict__ xhat,
                               const float* __restrict__ c,
                               float* __restrict__ v, int use_c)
{
    int o = blockIdx.x, b = blockIdx.y, tid = threadIdx.x;
    int d = tid & 15, ig = tid >> 4;
    const float* xb = xhat + ((size_t)(b * 100 + o)) * 1152 * 16;
    float acc = 0.f;
    if (use_c) {
        const float* cb = c + ((size_t)(b * 100 + o)) * 1152;
        for (int i = ig; i < 1152; i += 16)
            acc = fmaf(cb[i], xb[i * 16 + d], acc);
    } else {
        for (int i = ig; i < 1152; i += 16)
            acc += xb[i * 16 + d];
    }
    __shared__ float red[256];
    red[tid] = acc;
    __syncthreads();
    for (int st = 128; st >= 16; st >>= 1) {
        if (tid < st) red[tid] += red[tid + st];
        __syncthreads();
    }
    if (tid < 16) {
        float s = red[tid];
        if (!use_c) s *= 0.01f;
        float n2 = s * s;
        #pragma unroll
        for (int off = 8; off > 0; off >>= 1)
            n2 += __shfl_xor_sync(0xffffffffu, n2, off);
        float sc = (n2 / (1.f + n2)) * rsqrtf(n2 + 1e-8f);
        v[((size_t)(b * 100 + o)) * 16 + tid] = s * sc;
    }
}

// ---------------------------------------------------------------------------
// b-logit update: blog[b,o,i] (+)= sum_d xhat[b,o,i,d] * v[b,o,d]
// ---------------------------------------------------------------------------
__global__ void route_bupd_kernel(const float* __restrict__ xhat,
                                  const float* __restrict__ v,
                                  float* __restrict__ blog, int first)
{
    int o = blockIdx.x, b = blockIdx.y, tid = threadIdx.x;
    __shared__ float vs[16];
    if (tid < 16) vs[tid] = v[((size_t)(b * 100 + o)) * 16 + tid];
    __syncthreads();
    const float* xb = xhat + ((size_t)(b * 100 + o)) * 1152 * 16;
    float* bl = blog + ((size_t)(b * 100 + o)) * 1152;
    for (int i = tid; i < 1152; i += 256) {
        const float4* xp = reinterpret_cast<const float4*>(xb + (size_t)i * 16);
        float dot = 0.f;
        #pragma unroll
        for (int q = 0; q < 4; q++) {
            float4 x4 = xp[q];
            dot = fmaf(x4.x, vs[q * 4 + 0], dot);
            dot = fmaf(x4.y, vs[q * 4 + 1], dot);
            dot = fmaf(x4.z, vs[q * 4 + 2], dot);
            dot = fmaf(x4.w, vs[q * 4 + 3], dot);
        }
        bl[i] = first ? dot : (bl[i] + dot);
    }
}

// ---------------------------------------------------------------------------
// Softmax over o (100 entries) for each (b, i). Tile transpose via smem.
// grid (36 i-chunks, B); block 128.
// ---------------------------------------------------------------------------
__global__ void softmax_o_kernel(const float* __restrict__ blog, float* __restrict__ c)
{
    __shared__ float t[100][33];
    int i0 = blockIdx.x * 32, b = blockIdx.y, tid = threadIdx.x;
    for (int idx = tid; idx < 100 * 32; idx += 128) {
        int ii = idx % 32, o = idx / 32;
        t[o][ii] = blog[((size_t)(b * 100 + o)) * 1152 + i0 + ii];
    }
    __syncthreads();
    if (tid < 32) {
        float mx = -1e30f;
        for (int o = 0; o < 100; o++) mx = fmaxf(mx, t[o][tid]);
        float sm = 0.f;
        for (int o = 0; o < 100; o++) {
            float e = expf(t[o][tid] - mx);
            t[o][tid] = e;
            sm += e;
        }
        float inv = 1.f / sm;
        for (int o = 0; o < 100; o++) t[o][tid] *= inv;
    }
    __syncthreads();
    for (int idx = tid; idx < 100 * 32; idx += 128) {
        int ii = idx % 32, o = idx / 32;
        c[((size_t)(b * 100 + o)) * 1152 + i0 + ii] = t[o][ii];
    }
}

// ---------------------------------------------------------------------------
// FC: C[m,n] = act(A[m,:] @ W[:,n] + bias[n]); 64x64 tiles, 4x4 micro-tile.
// ---------------------------------------------------------------------------
template<bool RELU>
__global__ void fc_kernel(const float* __restrict__ A, const float* __restrict__ Wm,
                          const float* __restrict__ bias, float* __restrict__ C,
                          int K, int N)
{
    __shared__ __align__(16) float As[16][68];
    __shared__ __align__(16) float Bs[16][68];
    int tid = threadIdx.x;
    int n0 = blockIdx.x * 64, m0 = blockIdx.y * 64;
    int tx = tid % 16, ty = tid / 16;
    float acc[4][4];
    #pragma unroll
    for (int i = 0; i < 4; i++)
        #pragma unroll
        for (int j = 0; j < 4; j++) acc[i][j] = 0.f;

    for (int k0 = 0; k0 < K; k0 += 16) {
        #pragma unroll
        for (int rep = 0; rep < 4; rep++) {
            int idx = tid + rep * 256;
            int b_l = idx / 16, k_l = idx % 16;
            As[k_l][b_l] = A[(size_t)(m0 + b_l) * K + k0 + k_l];
        }
        #pragma unroll
        for (int rep = 0; rep < 4; rep++) {
            int idx = tid + rep * 256;
            int k_l = idx / 64, n_l = idx % 64;
            int n = n0 + n_l;
            Bs[k_l][n_l] = (n < N) ? Wm[(size_t)(k0 + k_l) * N + n] : 0.f;
        }
        __syncthreads();
        #pragma unroll
        for (int k = 0; k < 16; k++) {
            float4 a4 = *reinterpret_cast<const float4*>(&As[k][ty * 4]);
            float4 b4 = *reinterpret_cast<const float4*>(&Bs[k][tx * 4]);
            float a[4] = {a4.x, a4.y, a4.z, a4.w};
            float bb[4] = {b4.x, b4.y, b4.z, b4.w};
            #pragma unroll
            for (int i = 0; i < 4; i++)
                #pragma unroll
                for (int j = 0; j < 4; j++)
                    acc[i][j] = fmaf(a[i], bb[j], acc[i][j]);
        }
        __syncthreads();
    }
    #pragma unroll
    for (int i = 0; i < 4; i++) {
        int m = m0 + ty * 4 + i;
        #pragma unroll
        for (int j = 0; j < 4; j++) {
            int n = n0 + tx * 4 + j;
            if (n < N) {
                float val = acc[i][j] + bias[n];
                if (RELU) val = fmaxf(val, 0.f);
                C[(size_t)m * N + n] = val;
            }
        }
    }
}

// ---------------------------------------------------------------------------
// launch
// ---------------------------------------------------------------------------
extern "C" void kernel_launch(void* const* d_in, const int* in_sizes, int n_in,
                              void* d_out, int out_size)
{
    const float* x     = (const float*)d_in[0];
    const float* cw1   = (const float*)d_in[1];
    const float* cb1   = (const float*)d_in[2];
    const float* cw2   = (const float*)d_in[3];
    const float* cb2   = (const float*)d_in[4];
    const float* cw3   = (const float*)d_in[5];
    const float* cb3   = (const float*)d_in[6];
    const float* pw    = (const float*)d_in[7];
    const float* pb    = (const float*)d_in[8];
    const float* Wcaps = (const float*)d_in[9];
    const float* fw1   = (const float*)d_in[10];
    const float* fb1   = (const float*)d_in[11];
    const float* fw2   = (const float*)d_in[12];
    const float* fb2   = (const float*)d_in[13];
    const float* fw3   = (const float*)d_in[14];
    const float* fb3   = (const float*)d_in[15];

    void* sp = nullptr;
    cudaGetSymbolAddress(&sp, g_scratch);
    float* S    = (float*)sp;
    float* buf1 = S + O_BUF1;
    float* buf2 = S + O_BUF2;
    float* buf3 = S + O_BUF3;
    float* buf4 = S + O_BUF4;
    float* buf5 = S + O_BUF5;
    float* buf6 = S + O_BUF6;
    float* u    = S + O_U;
    float* xhat = S + O_XHAT;
    float* blog = S + O_BLOG;
    float* cbuf = S + O_C;
    float* v    = S + O_V;
    float* f1   = S + O_F1;
    float* f2   = S + O_F2;
    float* outp = (float*)d_out;

    // conv1: 3->96, 32x32, pad1, relu
    conv3x3_kernel<3, 32, 32, 96, 32, 32, 1, 3, 4, 1, true>
        <<<dim3(12, BATCH), 256>>>(x, cw1, cb1, buf1);
    // pool1 -> [B,96,16,16]
    maxpool_kernel<96, 32><<<(BATCH * 96 * 16 * 16 + 255) / 256, 256>>>(buf1, buf2);
    // conv2: 96->256, 16x16, pad1, relu
    conv3x3_kernel<96, 16, 16, 256, 16, 16, 1, 8, 4, 4, true>
        <<<dim3(8, BATCH), 256>>>(buf2, cw2, cb2, buf3);
    // pool2 -> [B,256,8,8]
    maxpool_kernel<256, 16><<<(BATCH * 256 * 8 * 8 + 255) / 256, 256>>>(buf3, buf4);
    // conv3: 256->384, 8x8, pad1, relu
    conv3x3_kernel<256, 8, 8, 384, 8, 8, 1, 8, 4, 16, true>
        <<<dim3(3, BATCH), 256>>>(buf4, cw3, cb3, buf5);
    // primarycaps conv: 384->256, 8x8 -> 6x6, pad0, no relu
    conv3x3_kernel<384, 8, 8, 256, 6, 6, 0, 8, 6, 16, false>
        <<<dim3(2, BATCH), 96>>>(buf5, pw, pb, buf6);
    // squash -> u [B,1152,8]
    squash_u_kernel<<<(BATCH * 1152 + 255) / 256, 256>>>(buf6, u);
    // x_hat [B,100,1152,16]
    xhat_kernel<<<dim3(36, 100), 256>>>(Wcaps, u, xhat);

    // routing iteration 0 (uniform c)
    route_s_kernel<<<dim3(100, BATCH), 256>>>(xhat, cbuf, v, 0);
    route_bupd_kernel<<<dim3(100, BATCH), 256>>>(xhat, v, blog, 1);
    // iteration 1
    softmax_o_kernel<<<dim3(36, BATCH), 128>>>(blog, cbuf);
    route_s_kernel<<<dim3(100, BATCH), 256>>>(xhat, cbuf, v, 1);
    route_bupd_kernel<<<dim3(100, BATCH), 256>>>(xhat, v, blog, 0);
    // iteration 2 (final)
    softmax_o_kernel<<<dim3(36, BATCH), 128>>>(blog, cbuf);
    route_s_kernel<<<dim3(100, BATCH), 256>>>(xhat, cbuf, v, 1);

    // FC head: v flat [B,1600]
    fc_kernel<true><<<dim3(64, 2), 256>>>(v, fw1, fb1, f1, 1600, 4096);
    fc_kernel<true><<<dim3(64, 2), 256>>>(f1, fw2, fb2, f2, 4096, 4096);
    fc_kernel<false><<<dim3(2, 2), 256>>>(f2, fw3, fb3, outp, 4096, 100);

    (void)in_sizes; (void)n_in; (void)out_size;
}

// round 4
// speedup vs baseline: 1.2776x; 1.2776x over previous
#include <cuda_runtime.h>
#include <cuda_fp16.h>
#include <cstddef>
#include <cstdint>
#include <math.h>

#define BATCH 128

// ---------------------------------------------------------------------------
// Scratch (no allocations allowed): fp32 scratch + fp16 xhat.
// ---------------------------------------------------------------------------
constexpr size_t N_BUF1 = (size_t)BATCH * 96 * 32 * 32;   // conv1 out
constexpr size_t N_BUF2 = (size_t)BATCH * 96 * 16 * 16;   // pool1
constexpr size_t N_BUF3 = (size_t)BATCH * 256 * 16 * 16;  // conv2 out
constexpr size_t N_BUF4 = (size_t)BATCH * 256 * 8 * 8;    // pool2
constexpr size_t N_BUF5 = (size_t)BATCH * 384 * 8 * 8;    // conv3 out
constexpr size_t N_BUF6 = (size_t)BATCH * 256 * 6 * 6;    // pcaps out
constexpr size_t N_U    = (size_t)BATCH * 1152 * 8;       // squashed caps
constexpr size_t N_BLOG = (size_t)BATCH * 100 * 1152;
constexpr size_t N_C    = (size_t)BATCH * 100 * 1152;
constexpr size_t N_V    = (size_t)BATCH * 100 * 16;
constexpr size_t N_F1   = (size_t)BATCH * 4096;
constexpr size_t N_F2   = (size_t)BATCH * 4096;
constexpr size_t N_XHAT = (size_t)BATCH * 100 * 1152 * 16;

constexpr size_t O_BUF1 = 0;
constexpr size_t O_BUF2 = O_BUF1 + N_BUF1;
constexpr size_t O_BUF3 = O_BUF2 + N_BUF2;
constexpr size_t O_BUF4 = O_BUF3 + N_BUF3;
constexpr size_t O_BUF5 = O_BUF4 + N_BUF4;
constexpr size_t O_BUF6 = O_BUF5 + N_BUF5;
constexpr size_t O_U    = O_BUF6 + N_BUF6;
constexpr size_t O_BLOG = O_U + N_U;
constexpr size_t O_C    = O_BLOG + N_BLOG;
constexpr size_t O_V    = O_C + N_C;
constexpr size_t O_F1   = O_V + N_V;
constexpr size_t O_F2   = O_F1 + N_F1;
constexpr size_t N_TOTAL = O_F2 + N_F2;

__device__ __align__(16) float g_scratch[N_TOTAL];
__device__ __align__(16) __half g_xhat[N_XHAT];

// ---------------------------------------------------------------------------
// Generic direct 3x3 conv (stride 1). Register-blocked: each thread computes
// PPT consecutive pixels in a row x 8 output channels.
// ---------------------------------------------------------------------------
template<int CIN, int HIN, int WIN, int COUT, int HOUT, int WOUT, int PAD,
         int ICC, int PPT, int NOCSUB, bool RELU>
__global__ void conv3x3_kernel(const float* __restrict__ in,
                               const float* __restrict__ wt,
                               const float* __restrict__ bias,
                               float* __restrict__ out)
{
    constexpr int NPG = (HOUT * WOUT) / PPT;
    constexpr int NT  = NPG * NOCSUB;
    constexpr int OCB = NOCSUB * 8;
    constexpr int HT  = HIN + 2 * PAD;
    constexpr int WT  = WIN + 2 * PAD;
    constexpr int WTP = WT + 1;

    __shared__ __align__(16) float in_s[ICC * HT * WTP];
    __shared__ __align__(16) float w_s[ICC * 9 * OCB];

    const int tid   = threadIdx.x;
    const int ocblk = blockIdx.x;
    const int b     = blockIdx.y;

    const int pg   = tid % NPG;
    const int ocs  = tid / NPG;
    const int row  = pg / (WOUT / PPT);
    const int col0 = (pg % (WOUT / PPT)) * PPT;
    const int oc0  = ocblk * OCB + ocs * 8;

    float acc[PPT][8];
    #pragma unroll
    for (int j = 0; j < 8; j++) {
        float bj = bias[oc0 + j];
        #pragma unroll
        for (int p = 0; p < PPT; p++) acc[p][j] = bj;
    }

    for (int ic0 = 0; ic0 < CIN; ic0 += ICC) {
        __syncthreads();
        for (int idx = tid; idx < ICC * HT * WT; idx += NT) {
            int x  = idx % WT;
            int y  = (idx / WT) % HT;
            int ic = idx / (WT * HT);
            int gy = y - PAD, gx = x - PAD;
            float v = 0.f;
            if (gy >= 0 && gy < HIN && gx >= 0 && gx < WIN)
                v = in[((size_t)(b * CIN + ic0 + ic) * HIN + gy) * WIN + gx];
            in_s[(ic * HT + y) * WTP + x] = v;
        }
        for (int idx = tid; idx < ICC * 9 * OCB; idx += NT) {
            int oc_l = idx % OCB;
            int tap  = (idx / OCB) % 9;
            int ic   = idx / (OCB * 9);
            w_s[(ic * 9 + tap) * OCB + oc_l] =
                wt[((size_t)(ocblk * OCB + oc_l) * CIN + ic0 + ic) * 9 + tap];
        }
        __syncthreads();

        #pragma unroll
        for (int ic = 0; ic < ICC; ic++) {
            #pragma unroll
            for (int ky = 0; ky < 3; ky++) {
                #pragma unroll
                for (int kx = 0; kx < 3; kx++) {
                    const float4* wp = reinterpret_cast<const float4*>(
                        &w_s[(ic * 9 + ky * 3 + kx) * OCB + ocs * 8]);
                    float4 wA = wp[0];
                    float4 wB = wp[1];
                    #pragma unroll
                    for (int p = 0; p < PPT; p++) {
                        float xv = in_s[(ic * HT + row + ky) * WTP + col0 + p + kx];
                        acc[p][0] = fmaf(xv, wA.x, acc[p][0]);
                        acc[p][1] = fmaf(xv, wA.y, acc[p][1]);
                        acc[p][2] = fmaf(xv, wA.z, acc[p][2]);
                        acc[p][3] = fmaf(xv, wA.w, acc[p][3]);
                        acc[p][4] = fmaf(xv, wB.x, acc[p][4]);
                        acc[p][5] = fmaf(xv, wB.y, acc[p][5]);
                        acc[p][6] = fmaf(xv, wB.z, acc[p][6]);
                        acc[p][7] = fmaf(xv, wB.w, acc[p][7]);
                    }
                }
            }
        }
    }

    #pragma unroll
    for (int j = 0; j < 8; j++) {
        #pragma unroll
        for (int p = 0; p < PPT; p++) {
            float v = acc[p][j];
            if (RELU) v = fmaxf(v, 0.f);
            out[((size_t)(b * COUT + oc0 + j) * HOUT + row) * WOUT + col0 + p] = v;
        }
    }
}

// ---------------------------------------------------------------------------
// MaxPool 3x3 stride 2 pad 1 (torch semantics)
// ---------------------------------------------------------------------------
template<int C, int HIN>
__global__ void maxpool_kernel(const float* __restrict__ in, float* __restrict__ out)
{
    constexpr int HO = HIN / 2;
    int idx = blockIdx.x * blockDim.x + threadIdx.x;
    if (idx >= BATCH * C * HO * HO) return;
    int ox = idx % HO;
    int oy = (idx / HO) % HO;
    int c  = (idx / (HO * HO)) % C;
    int b  = idx / (HO * HO * C);
    const float* p = in + ((size_t)(b * C + c)) * HIN * HIN;
    float m = -1e30f;
    #pragma unroll
    for (int dy = 0; dy < 3; dy++) {
        int y = 2 * oy - 1 + dy;
        if (y < 0 || y >= HIN) continue;
        #pragma unroll
        for (int dx = 0; dx < 3; dx++) {
            int x = 2 * ox - 1 + dx;
            if (x < 0 || x >= HIN) continue;
            m = fmaxf(m, p[y * HIN + x]);
        }
    }
    out[idx] = m;
}

// ---------------------------------------------------------------------------
// Squash primarycaps: p flat [B,9216] -> u [B,1152,8]
// ---------------------------------------------------------------------------
__global__ void squash_u_kernel(const float* __restrict__ p, float* __restrict__ u)
{
    int cap = blockIdx.x * blockDim.x + threadIdx.x;
    if (cap >= BATCH * 1152) return;
    const float4* s = reinterpret_cast<const float4*>(p + (size_t)cap * 8);
    float4 a = s[0], b4 = s[1];
    float n2 = a.x * a.x + a.y * a.y + a.z * a.z + a.w * a.w +
               b4.x * b4.x + b4.y * b4.y + b4.z * b4.z + b4.w * b4.w;
    float sc = (n2 / (1.f + n2)) * rsqrtf(n2 + 1e-8f);
    float4* o = reinterpret_cast<float4*>(u + (size_t)cap * 8);
    o[0] = make_float4(a.x * sc, a.y * sc, a.z * sc, a.w * sc);
    o[1] = make_float4(b4.x * sc, b4.y * sc, b4.z * sc, b4.w * sc);
}

// ---------------------------------------------------------------------------
// x_hat[b,o,i,d] = sum_e W[o,i,d,e] * u[b,i,e], stored fp16.
// grid (36 i-chunks, 100 o); block 256. Each thread owns (i_local, d-pair):
// 16 W values live in registers across the whole batch loop.
// ---------------------------------------------------------------------------
__global__ void xhat16_kernel(const float* __restrict__ Wc,
                              const float* __restrict__ u,
                              __half* __restrict__ xh)
{
    __shared__ float u_s[256];
    const int o  = blockIdx.y;
    const int i0 = blockIdx.x * 32;
    const int tid = threadIdx.x;
    const int il  = tid >> 3;   // 0..31 local input-cap
    const int dp  = tid & 7;    // d-pair index (d = 2*dp, 2*dp+1)

    const float4* wg4 = reinterpret_cast<const float4*>(
        Wc + (((size_t)o * 1152 + i0 + il) * 16 + dp * 2) * 8);
    float4 w0 = wg4[0], w1 = wg4[1], w2 = wg4[2], w3 = wg4[3];
    float wA[8] = {w0.x, w0.y, w0.z, w0.w, w1.x, w1.y, w1.z, w1.w};
    float wB[8] = {w2.x, w2.y, w2.z, w2.w, w3.x, w3.y, w3.z, w3.w};

    for (int b = 0; b < BATCH; b++) {
        __syncthreads();
        u_s[tid] = u[((size_t)b * 1152 + i0) * 8 + tid];
        __syncthreads();
        const float* ur = &u_s[il * 8];
        float a0 = 0.f, a1 = 0.f;
        #pragma unroll
        for (int e = 0; e < 8; e++) {
            a0 = fmaf(wA[e], ur[e], a0);
            a1 = fmaf(wB[e], ur[e], a1);
        }
        *reinterpret_cast<__half2*>(
            xh + (((size_t)b * 100 + o) * 1152 + i0 + il) * 16 + dp * 2) =
            __floats2half2_rn(a0, a1);
    }
}

// ---------------------------------------------------------------------------
// Fused routing iteration. Block = (o, b). Loads xhat[b,o] (36KB fp16) into
// smem ONCE, computes s -> squash -> v in-block, then the b-logit update
// from smem. MODE 0: uniform c (iter0), write blog. MODE 1: c from softmax,
// blog += update. MODE 2: final iter, write v only.
// Squash reduction uses smem only — NO partial-warp shuffles (all barriers
// are executed by the full block).
// ---------------------------------------------------------------------------
template<int MODE>
__global__ void route_fused_kernel(const __half* __restrict__ xhat,
                                   const float* __restrict__ c,
                                   float* __restrict__ blog,
                                   float* __restrict__ v)
{
    __shared__ __align__(16) __half xs[1152 * 16];
    __shared__ float cs[1152];
    __shared__ float red[256];
    __shared__ float vs[16];

    const int o = blockIdx.x, b = blockIdx.y, tid = threadIdx.x;
    const size_t base = (size_t)(b * 100 + o);

    // load xhat slab (36 KB) via float4 (8 halves each)
    const float4* xg = reinterpret_cast<const float4*>(xhat + base * 1152 * 16);
    float4* xs4 = reinterpret_cast<float4*>(xs);
    #pragma unroll
    for (int k = 0; k < 9; k++) xs4[tid + k * 256] = xg[tid + k * 256];

    if (MODE != 0) {
        const float* cg = c + base * 1152;
        for (int i = tid; i < 1152; i += 256) cs[i] = cg[i];
    }
    __syncthreads();

    // s[d] = sum_i c[i] * xhat[i][d]
    const int d = tid & 15, ig = tid >> 4;
    float acc = 0.f;
    for (int i = ig; i < 1152; i += 16) {
        float x = __half2float(xs[i * 16 + d]);
        if (MODE == 0) acc += x;
        else           acc = fmaf(cs[i], x, acc);
    }
    red[tid] = acc;
    __syncthreads();
    #pragma unroll
    for (int st = 128; st >= 16; st >>= 1) {
        if (tid < st) red[tid] += red[tid + st];
        __syncthreads();
    }
    // red[0..15] now hold s[d]. Scale (iter0) in-place, then squash via smem.
    if (tid < 16) {
        float s = red[tid];
        if (MODE == 0) s *= 0.01f;
        red[tid] = s;
    }
    __syncthreads();
    if (tid < 16) {
        float n2 = 0.f;
        #pragma unroll
        for (int q = 0; q < 16; q++) n2 += red[q] * red[q];
        float sc = (n2 / (1.f + n2)) * rsqrtf(n2 + 1e-8f);
        float vv = red[tid] * sc;
        vs[tid] = vv;
        if (MODE == 2) v[base * 16 + tid] = vv;
    }
    if (MODE == 2) return;
    __syncthreads();

    // blog[i] (+)= sum_d xhat[i][d] * v[d]
    float* bl = blog + base * 1152;
    for (int i = tid; i < 1152; i += 256) {
        const float4* xp = reinterpret_cast<const float4*>(xs + i * 16);
        float4 p0 = xp[0], p1 = xp[1];
        const __half2* h0 = reinterpret_cast<const __half2*>(&p0);
        const __half2* h1 = reinterpret_cast<const __half2*>(&p1);
        float dot = 0.f;
        #pragma unroll
        for (int q = 0; q < 4; q++) {
            float2 f = __half22float2(h0[q]);
            dot = fmaf(f.x, vs[q * 2 + 0], dot);
            dot = fmaf(f.y, vs[q * 2 + 1], dot);
        }
        #pragma unroll
        for (int q = 0; q < 4; q++) {
            float2 f = __half22float2(h1[q]);
            dot = fmaf(f.x, vs[8 + q * 2 + 0], dot);
            dot = fmaf(f.y, vs[8 + q * 2 + 1], dot);
        }
        if (MODE == 0) bl[i] = dot;
        else           bl[i] += dot;
    }
}

// ---------------------------------------------------------------------------
// Softmax over o (100 entries) for each (b, i). Tile transpose via smem.
// ---------------------------------------------------------------------------
__global__ void softmax_o_kernel(const float* __restrict__ blog, float* __restrict__ c)
{
    __shared__ float t[100][33];
    int i0 = blockIdx.x * 32, b = blockIdx.y, tid = threadIdx.x;
    for (int idx = tid; idx < 100 * 32; idx += 128) {
        int ii = idx % 32, o = idx / 32;
        t[o][ii] = blog[((size_t)(b * 100 + o)) * 1152 + i0 + ii];
    }
    __syncthreads();
    if (tid < 32) {
        float mx = -1e30f;
        for (int o = 0; o < 100; o++) mx = fmaxf(mx, t[o][tid]);
        float sm = 0.f;
        for (int o = 0; o < 100; o++) {
            float e = expf(t[o][tid] - mx);
            t[o][tid] = e;
            sm += e;
        }
        float inv = 1.f / sm;
        for (int o = 0; o < 100; o++) t[o][tid] *= inv;
    }
    __syncthreads();
    for (int idx = tid; idx < 100 * 32; idx += 128) {
        int ii = idx % 32, o = idx / 32;
        c[((size_t)(b * 100 + o)) * 1152 + i0 + ii] = t[o][ii];
    }
}

// ---------------------------------------------------------------------------
// FC: C[m,n] = act(A[m,:] @ W[:,n] + bias[n]); 64x64 tiles, 4x4 micro-tile.
// ---------------------------------------------------------------------------
template<bool RELU>
__global__ void fc_kernel(const float* __restrict__ A, const float* __restrict__ Wm,
                          const float* __restrict__ bias, float* __restrict__ C,
                          int K, int N)
{
    __shared__ __align__(16) float As[16][68];
    __shared__ __align__(16) float Bs[16][68];
    int tid = threadIdx.x;
    int n0 = blockIdx.x * 64, m0 = blockIdx.y * 64;
    int tx = tid % 16, ty = tid / 16;
    float acc[4][4];
    #pragma unroll
    for (int i = 0; i < 4; i++)
        #pragma unroll
        for (int j = 0; j < 4; j++) acc[i][j] = 0.f;

    for (int k0 = 0; k0 < K; k0 += 16) {
        #pragma unroll
        for (int rep = 0; rep < 4; rep++) {
            int idx = tid + rep * 256;
            int b_l = idx / 16, k_l = idx % 16;
            As[k_l][b_l] = A[(size_t)(m0 + b_l) * K + k0 + k_l];
        }
        #pragma unroll
        for (int rep = 0; rep < 4; rep++) {
            int idx = tid + rep * 256;
            int k_l = idx / 64, n_l = idx % 64;
            int n = n0 + n_l;
            Bs[k_l][n_l] = (n < N) ? Wm[(size_t)(k0 + k_l) * N + n] : 0.f;
        }
        __syncthreads();
        #pragma unroll
        for (int k = 0; k < 16; k++) {
            float4 a4 = *reinterpret_cast<const float4*>(&As[k][ty * 4]);
            float4 b4 = *reinterpret_cast<const float4*>(&Bs[k][tx * 4]);
            float a[4] = {a4.x, a4.y, a4.z, a4.w};
            float bb[4] = {b4.x, b4.y, b4.z, b4.w};
            #pragma unroll
            for (int i = 0; i < 4; i++)
                #pragma unroll
                for (int j = 0; j < 4; j++)
                    acc[i][j] = fmaf(a[i], bb[j], acc[i][j]);
        }
        __syncthreads();
    }
    #pragma unroll
    for (int i = 0; i < 4; i++) {
        int m = m0 + ty * 4 + i;
        #pragma unroll
        for (int j = 0; j < 4; j++) {
            int n = n0 + tx * 4 + j;
            if (n < N) {
                float val = acc[i][j] + bias[n];
                if (RELU) val = fmaxf(val, 0.f);
                C[(size_t)m * N + n] = val;
            }
        }
    }
}

// ---------------------------------------------------------------------------
// launch
// ---------------------------------------------------------------------------
extern "C" void kernel_launch(void* const* d_in, const int* in_sizes, int n_in,
                              void* d_out, int out_size)
{
    const float* x     = (const float*)d_in[0];
    const float* cw1   = (const float*)d_in[1];
    const float* cb1   = (const float*)d_in[2];
    const float* cw2   = (const float*)d_in[3];
    const float* cb2   = (const float*)d_in[4];
    const float* cw3   = (const float*)d_in[5];
    const float* cb3   = (const float*)d_in[6];
    const float* pw    = (const float*)d_in[7];
    const float* pb    = (const float*)d_in[8];
    const float* Wcaps = (const float*)d_in[9];
    const float* fw1   = (const float*)d_in[10];
    const float* fb1   = (const float*)d_in[11];
    const float* fw2   = (const float*)d_in[12];
    const float* fb2   = (const float*)d_in[13];
    const float* fw3   = (const float*)d_in[14];
    const float* fb3   = (const float*)d_in[15];

    void* sp = nullptr;
    cudaGetSymbolAddress(&sp, g_scratch);
    float* S    = (float*)sp;
    void* xp = nullptr;
    cudaGetSymbolAddress(&xp, g_xhat);
    __half* xhat = (__half*)xp;

    float* buf1 = S + O_BUF1;
    float* buf2 = S + O_BUF2;
    float* buf3 = S + O_BUF3;
    float* buf4 = S + O_BUF4;
    float* buf5 = S + O_BUF5;
    float* buf6 = S + O_BUF6;
    float* u    = S + O_U;
    float* blog = S + O_BLOG;
    float* cbuf = S + O_C;
    float* v    = S + O_V;
    float* f1   = S + O_F1;
    float* f2   = S + O_F2;
    float* outp = (float*)d_out;

    // conv backbone
    conv3x3_kernel<3, 32, 32, 96, 32, 32, 1, 3, 4, 1, true>
        <<<dim3(12, BATCH), 256>>>(x, cw1, cb1, buf1);
    maxpool_kernel<96, 32><<<(BATCH * 96 * 16 * 16 + 255) / 256, 256>>>(buf1, buf2);
    conv3x3_kernel<96, 16, 16, 256, 16, 16, 1, 8, 4, 4, true>
        <<<dim3(8, BATCH), 256>>>(buf2, cw2, cb2, buf3);
    maxpool_kernel<256, 16><<<(BATCH * 256 * 8 * 8 + 255) / 256, 256>>>(buf3, buf4);
    conv3x3_kernel<256, 8, 8, 384, 8, 8, 1, 8, 4, 16, true>
        <<<dim3(3, BATCH), 256>>>(buf4, cw3, cb3, buf5);
    conv3x3_kernel<384, 8, 8, 256, 6, 6, 0, 8, 6, 16, false>
        <<<dim3(2, BATCH), 96>>>(buf5, pw, pb, buf6);
    squash_u_kernel<<<(BATCH * 1152 + 255) / 256, 256>>>(buf6, u);

    // xhat (fp16)
    xhat16_kernel<<<dim3(36, 100), 256>>>(Wcaps, u, xhat);

    // routing: 3 fused iterations, softmax between
    route_fused_kernel<0><<<dim3(100, BATCH), 256>>>(xhat, cbuf, blog, v);
    softmax_o_kernel<<<dim3(36, BATCH), 128>>>(blog, cbuf);
    route_fused_kernel<1><<<dim3(100, BATCH), 256>>>(xhat, cbuf, blog, v);
    softmax_o_kernel<<<dim3(36, BATCH), 128>>>(blog, cbuf);
    route_fused_kernel<2><<<dim3(100, BATCH), 256>>>(xhat, cbuf, blog, v);

    // FC head
    fc_kernel<true><<<dim3(64, 2), 256>>>(v, fw1, fb1, f1, 1600, 4096);
    fc_kernel<true><<<dim3(64, 2), 256>>>(f1, fw2, fb2, f2, 4096, 4096);
    fc_kernel<false><<<dim3(2, 2), 256>>>(f2, fw3, fb3, outp, 4096, 100);

    (void)in_sizes; (void)n_in; (void)out_size;
}

// round 5
// speedup vs baseline: 1.2966x; 1.0148x over previous
#include <cuda_runtime.h>
#include <cuda_fp16.h>
#include <cstddef>
#include <cstdint>
#include <math.h>

#define BATCH 128

// ---------------------------------------------------------------------------
// f32x2 packed-FMA helpers (sm_103a): 2 fp32 FMAs per issue slot, exact fp32.
// ---------------------------------------------------------------------------
__device__ __forceinline__ unsigned long long pack2(float lo, float hi) {
    unsigned long long r;
    asm("mov.b64 %0, {%1, %2};" : "=l"(r) : "f"(lo), "f"(hi));
    return r;
}
__device__ __forceinline__ void unpack2(unsigned long long v, float& lo, float& hi) {
    asm("mov.b64 {%0, %1}, %2;" : "=f"(lo), "=f"(hi) : "l"(v));
}
__device__ __forceinline__ unsigned long long ffma2(unsigned long long a,
                                                    unsigned long long b,
                                                    unsigned long long c) {
    unsigned long long d;
    asm("fma.rn.f32x2 %0, %1, %2, %3;" : "=l"(d) : "l"(a), "l"(b), "l"(c));
    return d;
}

// ---------------------------------------------------------------------------
// Scratch (no allocations allowed): fp32 scratch + fp16 xhat.
// ---------------------------------------------------------------------------
constexpr size_t N_BUF1 = (size_t)BATCH * 96 * 32 * 32;   // conv1 out
constexpr size_t N_BUF2 = (size_t)BATCH * 96 * 16 * 16;   // pool1
constexpr size_t N_BUF3 = (size_t)BATCH * 256 * 16 * 16;  // conv2 out
constexpr size_t N_BUF4 = (size_t)BATCH * 256 * 8 * 8;    // pool2
constexpr size_t N_BUF5 = (size_t)BATCH * 384 * 8 * 8;    // conv3 out
constexpr size_t N_BUF6 = (size_t)BATCH * 256 * 6 * 6;    // pcaps out
constexpr size_t N_U    = (size_t)BATCH * 1152 * 8;       // squashed caps
constexpr size_t N_BLOG = (size_t)BATCH * 100 * 1152;
constexpr size_t N_C    = (size_t)BATCH * 100 * 1152;
constexpr size_t N_V    = (size_t)BATCH * 100 * 16;
constexpr size_t N_F1   = (size_t)BATCH * 4096;
constexpr size_t N_F2   = (size_t)BATCH * 4096;
constexpr size_t N_XHAT = (size_t)BATCH * 100 * 1152 * 16;

constexpr size_t O_BUF1 = 0;
constexpr size_t O_BUF2 = O_BUF1 + N_BUF1;
constexpr size_t O_BUF3 = O_BUF2 + N_BUF2;
constexpr size_t O_BUF4 = O_BUF3 + N_BUF3;
constexpr size_t O_BUF5 = O_BUF4 + N_BUF4;
constexpr size_t O_BUF6 = O_BUF5 + N_BUF5;
constexpr size_t O_U    = O_BUF6 + N_BUF6;
constexpr size_t O_BLOG = O_U + N_U;
constexpr size_t O_C    = O_BLOG + N_BLOG;
constexpr size_t O_V    = O_C + N_C;
constexpr size_t O_F1   = O_V + N_V;
constexpr size_t O_F2   = O_F1 + N_F1;
constexpr size_t N_TOTAL = O_F2 + N_F2;

__device__ __align__(16) float g_scratch[N_TOTAL];
__device__ __align__(16) __half g_xhat[N_XHAT];

// ---------------------------------------------------------------------------
// Direct 3x3 conv (stride 1) with packed f32x2 FMAs.
// Each thread: PPT consecutive pixels x 8 output channels (4 oc-pairs).
// Input tile stored DUPLICATED ((v,v) as 8B) so LDS.64 yields the packed
// broadcast operand directly. Weights consecutive-oc -> natural pairs.
// ---------------------------------------------------------------------------
template<int CIN, int HIN, int WIN, int COUT, int HOUT, int WOUT, int PAD,
         int ICC, int PPT, int NOCSUB, bool RELU>
__global__ void conv3x3_kernel(const float* __restrict__ in,
                               const float* __restrict__ wt,
                               const float* __restrict__ bias,
                               float* __restrict__ out)
{
    constexpr int NPG = (HOUT * WOUT) / PPT;
    constexpr int NT  = NPG * NOCSUB;
    constexpr int OCB = NOCSUB * 8;
    constexpr int HT  = HIN + 2 * PAD;
    constexpr int WT  = WIN + 2 * PAD;
    constexpr int WTP = WT + 1;

    __shared__ __align__(16) unsigned long long in_s2[ICC * HT * WTP];
    __shared__ __align__(16) float w_s[ICC * 9 * OCB];

    const int tid   = threadIdx.x;
    const int ocblk = blockIdx.x;
    const int b     = blockIdx.y;

    const int pg   = tid % NPG;
    const int ocs  = tid / NPG;
    const int row  = pg / (WOUT / PPT);
    const int col0 = (pg % (WOUT / PPT)) * PPT;
    const int oc0  = ocblk * OCB + ocs * 8;

    unsigned long long acc2[PPT][4];
    #pragma unroll
    for (int j4 = 0; j4 < 4; j4++) {
        unsigned long long bp = pack2(bias[oc0 + 2 * j4], bias[oc0 + 2 * j4 + 1]);
        #pragma unroll
        for (int p = 0; p < PPT; p++) acc2[p][j4] = bp;
    }

    for (int ic0 = 0; ic0 < CIN; ic0 += ICC) {
        __syncthreads();
        // input tile (duplicated pack, zero padded)
        for (int idx = tid; idx < ICC * HT * WT; idx += NT) {
            int x  = idx % WT;
            int y  = (idx / WT) % HT;
            int ic = idx / (WT * HT);
            int gy = y - PAD, gx = x - PAD;
            float v = 0.f;
            if (gy >= 0 && gy < HIN && gx >= 0 && gx < WIN)
                v = in[((size_t)(b * CIN + ic0 + ic) * HIN + gy) * WIN + gx];
            in_s2[(ic * HT + y) * WTP + x] = pack2(v, v);
        }
        // weights: global layout [oc][ic][3][3] -> smem [ic][tap][oc]
        for (int idx = tid; idx < ICC * 9 * OCB; idx += NT) {
            int oc_l = idx % OCB;
            int tap  = (idx / OCB) % 9;
            int ic   = idx / (OCB * 9);
            w_s[(ic * 9 + tap) * OCB + oc_l] =
                wt[((size_t)(ocblk * OCB + oc_l) * CIN + ic0 + ic) * 9 + tap];
        }
        __syncthreads();

        #pragma unroll
        for (int ic = 0; ic < ICC; ic++) {
            #pragma unroll
            for (int ky = 0; ky < 3; ky++) {
                unsigned long long xq[PPT + 2];
                #pragma unroll
                for (int q = 0; q < PPT + 2; q++)
                    xq[q] = in_s2[(ic * HT + row + ky) * WTP + col0 + q];
                #pragma unroll
                for (int kx = 0; kx < 3; kx++) {
                    const ulonglong2* wp = reinterpret_cast<const ulonglong2*>(
                        &w_s[(ic * 9 + ky * 3 + kx) * OCB + ocs * 8]);
                    ulonglong2 wA = wp[0];   // pairs (w0,w1),(w2,w3)
                    ulonglong2 wB = wp[1];   // pairs (w4,w5),(w6,w7)
                    #pragma unroll
                    for (int p = 0; p < PPT; p++) {
                        unsigned long long xv = xq[p + kx];
                        acc2[p][0] = ffma2(xv, wA.x, acc2[p][0]);
                        acc2[p][1] = ffma2(xv, wA.y, acc2[p][1]);
                        acc2[p][2] = ffma2(xv, wB.x, acc2[p][2]);
                        acc2[p][3] = ffma2(xv, wB.y, acc2[p][3]);
                    }
                }
            }
        }
    }

    #pragma unroll
    for (int j4 = 0; j4 < 4; j4++) {
        #pragma unroll
        for (int p = 0; p < PPT; p++) {
            float lo, hi;
            unpack2(acc2[p][j4], lo, hi);
            if (RELU) { lo = fmaxf(lo, 0.f); hi = fmaxf(hi, 0.f); }
            out[((size_t)(b * COUT + oc0 + 2 * j4) * HOUT + row) * WOUT + col0 + p] = lo;
            out[((size_t)(b * COUT + oc0 + 2 * j4 + 1) * HOUT + row) * WOUT + col0 + p] = hi;
        }
    }
}

// ---------------------------------------------------------------------------
// MaxPool 3x3 stride 2 pad 1 (torch semantics)
// ---------------------------------------------------------------------------
template<int C, int HIN>
__global__ void maxpool_kernel(const float* __restrict__ in, float* __restrict__ out)
{
    constexpr int HO = HIN / 2;
    int idx = blockIdx.x * blockDim.x + threadIdx.x;
    if (idx >= BATCH * C * HO * HO) return;
    int ox = idx % HO;
    int oy = (idx / HO) % HO;
    int c  = (idx / (HO * HO)) % C;
    int b  = idx / (HO * HO * C);
    const float* p = in + ((size_t)(b * C + c)) * HIN * HIN;
    float m = -1e30f;
    #pragma unroll
    for (int dy = 0; dy < 3; dy++) {
        int y = 2 * oy - 1 + dy;
        if (y < 0 || y >= HIN) continue;
        #pragma unroll
        for (int dx = 0; dx < 3; dx++) {
            int x = 2 * ox - 1 + dx;
            if (x < 0 || x >= HIN) continue;
            m = fmaxf(m, p[y * HIN + x]);
        }
    }
    out[idx] = m;
}

// ---------------------------------------------------------------------------
// Squash primarycaps: p flat [B,9216] -> u [B,1152,8]
// ---------------------------------------------------------------------------
__global__ void squash_u_kernel(const float* __restrict__ p, float* __restrict__ u)
{
    int cap = blockIdx.x * blockDim.x + threadIdx.x;
    if (cap >= BATCH * 1152) return;
    const float4* s = reinterpret_cast<const float4*>(p + (size_t)cap * 8);
    float4 a = s[0], b4 = s[1];
    float n2 = a.x * a.x + a.y * a.y + a.z * a.z + a.w * a.w +
               b4.x * b4.x + b4.y * b4.y + b4.z * b4.z + b4.w * b4.w;
    float sc = (n2 / (1.f + n2)) * rsqrtf(n2 + 1e-8f);
    float4* o = reinterpret_cast<float4*>(u + (size_t)cap * 8);
    o[0] = make_float4(a.x * sc, a.y * sc, a.z * sc, a.w * sc);
    o[1] = make_float4(b4.x * sc, b4.y * sc, b4.z * sc, b4.w * sc);
}

// ---------------------------------------------------------------------------
// x_hat[b,o,i,d] = sum_e W[o,i,d,e] * u[b,i,e], stored fp16.
// ---------------------------------------------------------------------------
__global__ void xhat16_kernel(const float* __restrict__ Wc,
                              const float* __restrict__ u,
                              __half* __restrict__ xh)
{
    __shared__ float u_s[256];
    const int o  = blockIdx.y;
    const int i0 = blockIdx.x * 32;
    const int tid = threadIdx.x;
    const int il  = tid >> 3;   // 0..31 local input-cap
    const int dp  = tid & 7;    // d-pair index (d = 2*dp, 2*dp+1)

    const float4* wg4 = reinterpret_cast<const float4*>(
        Wc + (((size_t)o * 1152 + i0 + il) * 16 + dp * 2) * 8);
    float4 w0 = wg4[0], w1 = wg4[1], w2 = wg4[2], w3 = wg4[3];
    float wA[8] = {w0.x, w0.y, w0.z, w0.w, w1.x, w1.y, w1.z, w1.w};
    float wB[8] = {w2.x, w2.y, w2.z, w2.w, w3.x, w3.y, w3.z, w3.w};

    for (int b = 0; b < BATCH; b++) {
        __syncthreads();
        u_s[tid] = u[((size_t)b * 1152 + i0) * 8 + tid];
        __syncthreads();
        const float* ur = &u_s[il * 8];
        float a0 = 0.f, a1 = 0.f;
        #pragma unroll
        for (int e = 0; e < 8; e++) {
            a0 = fmaf(wA[e], ur[e], a0);
            a1 = fmaf(wB[e], ur[e], a1);
        }
        *reinterpret_cast<__half2*>(
            xh + (((size_t)b * 100 + o) * 1152 + i0 + il) * 16 + dp * 2) =
            __floats2half2_rn(a0, a1);
    }
}

// ---------------------------------------------------------------------------
// Fused routing iteration (smem-only squash reduction; all barriers uniform).
// ---------------------------------------------------------------------------
template<int MODE>
__global__ void route_fused_kernel(const __half* __restrict__ xhat,
                                   const float* __restrict__ c,
                                   float* __restrict__ blog,
                                   float* __restrict__ v)
{
    __shared__ __align__(16) __half xs[1152 * 16];
    __shared__ float cs[1152];
    __shared__ float red[256];
    __shared__ float vs[16];

    const int o = blockIdx.x, b = blockIdx.y, tid = threadIdx.x;
    const size_t base = (size_t)(b * 100 + o);

    const float4* xg = reinterpret_cast<const float4*>(xhat + base * 1152 * 16);
    float4* xs4 = reinterpret_cast<float4*>(xs);
    #pragma unroll
    for (int k = 0; k < 9; k++) xs4[tid + k * 256] = xg[tid + k * 256];

    if (MODE != 0) {
        const float* cg = c + base * 1152;
        for (int i = tid; i < 1152; i += 256) cs[i] = cg[i];
    }
    __syncthreads();

    const int d = tid & 15, ig = tid >> 4;
    float acc = 0.f;
    for (int i = ig; i < 1152; i += 16) {
        float x = __half2float(xs[i * 16 + d]);
        if (MODE == 0) acc += x;
        else           acc = fmaf(cs[i], x, acc);
    }
    red[tid] = acc;
    __syncthreads();
    #pragma unroll
    for (int st = 128; st >= 16; st >>= 1) {
        if (tid < st) red[tid] += red[tid + st];
        __syncthreads();
    }
    if (tid < 16) {
        float s = red[tid];
        if (MODE == 0) s *= 0.01f;
        red[tid] = s;
    }
    __syncthreads();
    if (tid < 16) {
        float n2 = 0.f;
        #pragma unroll
        for (int q = 0; q < 16; q++) n2 += red[q] * red[q];
        float sc = (n2 / (1.f + n2)) * rsqrtf(n2 + 1e-8f);
        float vv = red[tid] * sc;
        vs[tid] = vv;
        if (MODE == 2) v[base * 16 + tid] = vv;
    }
    if (MODE == 2) return;
    __syncthreads();

    float* bl = blog + base * 1152;
    for (int i = tid; i < 1152; i += 256) {
        const float4* xp = reinterpret_cast<const float4*>(xs + i * 16);
        float4 p0 = xp[0], p1 = xp[1];
        const __half2* h0 = reinterpret_cast<const __half2*>(&p0);
        const __half2* h1 = reinterpret_cast<const __half2*>(&p1);
        float dot = 0.f;
        #pragma unroll
        for (int q = 0; q < 4; q++) {
            float2 f = __half22float2(h0[q]);
            dot = fmaf(f.x, vs[q * 2 + 0], dot);
            dot = fmaf(f.y, vs[q * 2 + 1], dot);
        }
        #pragma unroll
        for (int q = 0; q < 4; q++) {
            float2 f = __half22float2(h1[q]);
            dot = fmaf(f.x, vs[8 + q * 2 + 0], dot);
            dot = fmaf(f.y, vs[8 + q * 2 + 1], dot);
        }
        if (MODE == 0) bl[i] = dot;
        else           bl[i] += dot;
    }
}

// ---------------------------------------------------------------------------
// Softmax over o (100 entries) for each (b, i).
// ---------------------------------------------------------------------------
__global__ void softmax_o_kernel(const float* __restrict__ blog, float* __restrict__ c)
{
    __shared__ float t[100][33];
    int i0 = blockIdx.x * 32, b = blockIdx.y, tid = threadIdx.x;
    for (int idx = tid; idx < 100 * 32; idx += 128) {
        int ii = idx % 32, o = idx / 32;
        t[o][ii] = blog[((size_t)(b * 100 + o)) * 1152 + i0 + ii];
    }
    __syncthreads();
    if (tid < 32) {
        float mx = -1e30f;
        for (int o = 0; o < 100; o++) mx = fmaxf(mx, t[o][tid]);
        float sm = 0.f;
        for (int o = 0; o < 100; o++) {
            float e = expf(t[o][tid] - mx);
            t[o][tid] = e;
            sm += e;
        }
        float inv = 1.f / sm;
        for (int o = 0; o < 100; o++) t[o][tid] *= inv;
    }
    __syncthreads();
    for (int idx = tid; idx < 100 * 32; idx += 128) {
        int ii = idx % 32, o = idx / 32;
        c[((size_t)(b * 100 + o)) * 1152 + i0 + ii] = t[o][ii];
    }
}

// ---------------------------------------------------------------------------
// FC with packed f32x2: C[m,n] = act(A[m,:] @ W[:,n] + bias[n]).
// 64x64 tiles, 4m x 4n micro-tile (2 f32x2 pairs per row).
// A stored duplicated (a,a) so LDS.64 yields packed broadcast operand.
// ---------------------------------------------------------------------------
template<bool RELU>
__global__ void fc_kernel(const float* __restrict__ A, const float* __restrict__ Wm,
                          const float* __restrict__ bias, float* __restrict__ C,
                          int K, int N)
{
    __shared__ __align__(16) unsigned long long As2[16][66];
    __shared__ __align__(16) float Bs[16][68];
    int tid = threadIdx.x;
    int n0 = blockIdx.x * 64, m0 = blockIdx.y * 64;
    int tx = tid % 16, ty = tid / 16;
    unsigned long long acc2[4][2];
    #pragma unroll
    for (int i = 0; i < 4; i++)
        #pragma unroll
        for (int j = 0; j < 2; j++) acc2[i][j] = 0ull;

    for (int k0 = 0; k0 < K; k0 += 16) {
        #pragma unroll
        for (int rep = 0; rep < 4; rep++) {
            int idx = tid + rep * 256;
            int b_l = idx / 16, k_l = idx % 16;
            float a = A[(size_t)(m0 + b_l) * K + k0 + k_l];
            As2[k_l][b_l] = pack2(a, a);
        }
        #pragma unroll
        for (int rep = 0; rep < 4; rep++) {
            int idx = tid + rep * 256;
            int k_l = idx / 64, n_l = idx % 64;
            int n = n0 + n_l;
            Bs[k_l][n_l] = (n < N) ? Wm[(size_t)(k0 + k_l) * N + n] : 0.f;
        }
        __syncthreads();
        #pragma unroll
        for (int k = 0; k < 16; k++) {
            const ulonglong2* bp = reinterpret_cast<const ulonglong2*>(&Bs[k][tx * 4]);
            ulonglong2 bb = bp[0];  // pairs (b0,b1),(b2,b3)
            unsigned long long a0 = As2[k][ty * 4 + 0];
            unsigned long long a1 = As2[k][ty * 4 + 1];
            unsigned long long a2 = As2[k][ty * 4 + 2];
            unsigned long long a3 = As2[k][ty * 4 + 3];
            acc2[0][0] = ffma2(a0, bb.x, acc2[0][0]);
            acc2[0][1] = ffma2(a0, bb.y, acc2[0][1]);
            acc2[1][0] = ffma2(a1, bb.x, acc2[1][0]);
            acc2[1][1] = ffma2(a1, bb.y, acc2[1][1]);
            acc2[2][0] = ffma2(a2, bb.x, acc2[2][0]);
            acc2[2][1] = ffma2(a2, bb.y, acc2[2][1]);
            acc2[3][0] = ffma2(a3, bb.x, acc2[3][0]);
            acc2[3][1] = ffma2(a3, bb.y, acc2[3][1]);
        }
        __syncthreads();
    }
    #pragma unroll
    for (int i = 0; i < 4; i++) {
        int m = m0 + ty * 4 + i;
        #pragma unroll
        for (int j = 0; j < 2; j++) {
            float lo, hi;
            unpack2(acc2[i][j], lo, hi);
            int n_lo = n0 + tx * 4 + 2 * j;
            int n_hi = n_lo + 1;
            if (n_lo < N) {
                float val = lo + bias[n_lo];
                if (RELU) val = fmaxf(val, 0.f);
                C[(size_t)m * N + n_lo] = val;
            }
            if (n_hi < N) {
                float val = hi + bias[n_hi];
                if (RELU) val = fmaxf(val, 0.f);
                C[(size_t)m * N + n_hi] = val;
            }
        }
    }
}

// ---------------------------------------------------------------------------
// launch
// ---------------------------------------------------------------------------
extern "C" void kernel_launch(void* const* d_in, const int* in_sizes, int n_in,
                              void* d_out, int out_size)
{
    const float* x     = (const float*)d_in[0];
    const float* cw1   = (const float*)d_in[1];
    const float* cb1   = (const float*)d_in[2];
    const float* cw2   = (const float*)d_in[3];
    const float* cb2   = (const float*)d_in[4];
    const float* cw3   = (const float*)d_in[5];
    const float* cb3   = (const float*)d_in[6];
    const float* pw    = (const float*)d_in[7];
    const float* pb    = (const float*)d_in[8];
    const float* Wcaps = (const float*)d_in[9];
    const float* fw1   = (const float*)d_in[10];
    const float* fb1   = (const float*)d_in[11];
    const float* fw2   = (const float*)d_in[12];
    const float* fb2   = (const float*)d_in[13];
    const float* fw3   = (const float*)d_in[14];
    const float* fb3   = (const float*)d_in[15];

    void* sp = nullptr;
    cudaGetSymbolAddress(&sp, g_scratch);
    float* S    = (float*)sp;
    void* xp = nullptr;
    cudaGetSymbolAddress(&xp, g_xhat);
    __half* xhat = (__half*)xp;

    float* buf1 = S + O_BUF1;
    float* buf2 = S + O_BUF2;
    float* buf3 = S + O_BUF3;
    float* buf4 = S + O_BUF4;
    float* buf5 = S + O_BUF5;
    float* buf6 = S + O_BUF6;
    float* u    = S + O_U;
    float* blog = S + O_BLOG;
    float* cbuf = S + O_C;
    float* v    = S + O_V;
    float* f1   = S + O_F1;
    float* f2   = S + O_F2;
    float* outp = (float*)d_out;

    // conv backbone
    conv3x3_kernel<3, 32, 32, 96, 32, 32, 1, 3, 4, 1, true>
        <<<dim3(12, BATCH), 256>>>(x, cw1, cb1, buf1);
    maxpool_kernel<96, 32><<<(BATCH * 96 * 16 * 16 + 255) / 256, 256>>>(buf1, buf2);
    conv3x3_kernel<96, 16, 16, 256, 16, 16, 1, 8, 4, 4, true>
        <<<dim3(8, BATCH), 256>>>(buf2, cw2, cb2, buf3);
    maxpool_kernel<256, 16><<<(BATCH * 256 * 8 * 8 + 255) / 256, 256>>>(buf3, buf4);
    conv3x3_kernel<256, 8, 8, 384, 8, 8, 1, 8, 4, 16, true>
        <<<dim3(3, BATCH), 256>>>(buf4, cw3, cb3, buf5);
    conv3x3_kernel<384, 8, 8, 256, 6, 6, 0, 8, 6, 16, false>
        <<<dim3(2, BATCH), 96>>>(buf5, pw, pb, buf6);
    squash_u_kernel<<<(BATCH * 1152 + 255) / 256, 256>>>(buf6, u);

    // xhat (fp16)
    xhat16_kernel<<<dim3(36, 100), 256>>>(Wcaps, u, xhat);

    // routing: 3 fused iterations, softmax between
    route_fused_kernel<0><<<dim3(100, BATCH), 256>>>(xhat, cbuf, blog, v);
    softmax_o_kernel<<<dim3(36, BATCH), 128>>>(blog, cbuf);
    route_fused_kernel<1><<<dim3(100, BATCH), 256>>>(xhat, cbuf, blog, v);
    softmax_o_kernel<<<dim3(36, BATCH), 128>>>(blog, cbuf);
    route_fused_kernel<2><<<dim3(100, BATCH), 256>>>(xhat, cbuf, blog, v);

    // FC head
    fc_kernel<true><<<dim3(64, 2), 256>>>(v, fw1, fb1, f1, 1600, 4096);
    fc_kernel<true><<<dim3(64, 2), 256>>>(f1, fw2, fb2, f2, 4096, 4096);
    fc_kernel<false><<<dim3(2, 2), 256>>>(f2, fw3, fb3, outp, 4096, 100);

    (void)in_sizes; (void)n_in; (void)out_size;
}